// round 2
// baseline (speedup 1.0000x reference)
#include <cuda_runtime.h>
#include <cuda_bf16.h>
#include <cstdint>

using bf16 = __nv_bfloat16;
using bf162 = __nv_bfloat162;

#define DEVFN __device__ __forceinline__

// ---------------- problem sizes ----------------
constexpr int B_SZ = 16, SEQ = 2048, DM = 512, DI = 1024, DS = 16;
constexpr int ROWS = B_SZ * SEQ;           // 32768
constexpr int N1 = 2 * DI;                 // 2048 (GEMM1 N)
constexpr int N2 = 1152;                   // GEMM2 padded N (1024 dt + 32 ssm + 96 pad)
constexpr int N3 = DM;                     // 512

// ---------------- scratch (device globals; no allocs allowed) ----------------
__device__ __align__(256) bf16  g_xb  [(size_t)ROWS * DM];        // clipped x, bf16
__device__ __align__(256) bf16  g_W1  [(size_t)N1 * DM];          // W_in bf16
__device__ __align__(256) bf16  g_xr  [(size_t)ROWS * N1];        // x_p | res
__device__ __align__(256) bf16  g_xc  [(size_t)ROWS * DI];        // conv+silu out
__device__ __align__(256) bf16  g_Wcat[(size_t)N2 * DI];          // [W_dt ; W_x ; 0]
__device__ __align__(256) float g_b2  [N2];                        // [b_dt ; 0]
__device__ __align__(256) bf16  g_dtbc[(size_t)ROWS * N2];        // dt | B | C
__device__ __align__(256) bf16  g_y   [(size_t)ROWS * DI];        // scan out
__device__ __align__(256) bf16  g_y2  [(size_t)ROWS * DI];        // y * silu(res)
__device__ __align__(256) bf16  g_W3  [(size_t)N3 * DI];          // W_out bf16
__device__ __align__(256) float g_opre[(size_t)ROWS * DM];        // pre-LN

// ---------------- small helpers ----------------
DEVFN float bf2f(bf16 v) { return __bfloat162float(v); }
DEVFN bf16  f2bf(float v) { return __float2bfloat16(v); }
DEVFN float2 bf2x(uint32_t u) {
    bf162 t = *reinterpret_cast<bf162*>(&u);
    return __bfloat1622float2(t);
}
DEVFN float ex2f(float x) { float r; asm("ex2.approx.f32 %0, %1;" : "=f"(r) : "f"(x)); return r; }
DEVFN float clip10(float x) { return fminf(fmaxf(x, -10.f), 10.f); }

DEVFN void cp16(void* s, const void* g) {
    unsigned sa = (unsigned)__cvta_generic_to_shared(s);
    asm volatile("cp.async.cg.shared.global [%0], [%1], 16;\n" :: "r"(sa), "l"(g));
}
DEVFN void ldm4(uint32_t* r, const void* p) {
    unsigned a = (unsigned)__cvta_generic_to_shared(p);
    asm volatile("ldmatrix.sync.aligned.m8n8.x4.shared.b16 {%0,%1,%2,%3}, [%4];\n"
                 : "=r"(r[0]), "=r"(r[1]), "=r"(r[2]), "=r"(r[3]) : "r"(a));
}
DEVFN void ldm2(uint32_t* r, const void* p) {
    unsigned a = (unsigned)__cvta_generic_to_shared(p);
    asm volatile("ldmatrix.sync.aligned.m8n8.x2.shared.b16 {%0,%1}, [%2];\n"
                 : "=r"(r[0]), "=r"(r[1]) : "r"(a));
}
DEVFN void mma16816(float* c, const uint32_t* a, const uint32_t* b) {
    asm volatile(
        "mma.sync.aligned.m16n8k16.row.col.f32.bf16.bf16.f32 "
        "{%0,%1,%2,%3}, {%4,%5,%6,%7}, {%8,%9}, {%0,%1,%2,%3};\n"
        : "+f"(c[0]), "+f"(c[1]), "+f"(c[2]), "+f"(c[3])
        : "r"(a[0]), "r"(a[1]), "r"(a[2]), "r"(a[3]), "r"(b[0]), "r"(b[1]));
}

// ---------------- prep kernels (write device globals from device code) -------
__global__ void k_cvtW1(const float* __restrict__ w) {
    int i = blockIdx.x * 256 + threadIdx.x;
    if (i < N1 * DM) g_W1[i] = f2bf(w[i]);
}
__global__ void k_cvtW3(const float* __restrict__ w) {
    int i = blockIdx.x * 256 + threadIdx.x;
    if (i < N3 * DI) g_W3[i] = f2bf(w[i]);
}
__global__ void k_wcat(const float* __restrict__ Wdt, const float* __restrict__ Wx) {
    int i = blockIdx.x * 256 + threadIdx.x;
    if (i >= N2 * DI) return;
    int n = i / DI, k = i % DI;
    float v = 0.f;
    if (n < 1024)       v = Wdt[n * DI + k];
    else if (n < 1056)  v = Wx[(n - 1024) * DI + k];
    g_Wcat[i] = f2bf(v);
}
__global__ void k_bias2(const float* __restrict__ bdt) {
    int i = blockIdx.x * 256 + threadIdx.x;
    if (i < N2) g_b2[i] = (i < 1024) ? bdt[i] : 0.f;
}
__global__ void k_clipx(const float* __restrict__ x) {
    int i = blockIdx.x * 256 + threadIdx.x;
    if (i < ROWS * DM) g_xb[i] = f2bf(clip10(x[i]));
}

// ---------------- bf16 GEMM: C[M,N] = A[M,K] @ B[N,K]^T  (128x128x32 tiles) --
// SEL 1: g_xb @ g_W1^T   -> g_xr (bf16)
// SEL 2: g_xc @ g_Wcat^T -> g_dtbc (bf16, +g_b2 bias)
// SEL 3: g_y2 @ g_W3^T   -> g_opre (f32, + clip(resid))
template <int SEL>
__global__ void __launch_bounds__(256) k_gemm(const float* __restrict__ resid)
{
    constexpr int N = (SEL == 1) ? N1 : (SEL == 2) ? N2 : N3;
    constexpr int K = (SEL == 1) ? DM : DI;
    const bf16* __restrict__ A  = (SEL == 1) ? g_xb : (SEL == 2) ? g_xc : g_y2;
    const bf16* __restrict__ Bw = (SEL == 1) ? g_W1 : (SEL == 2) ? g_Wcat : g_W3;

    __shared__ __align__(16) bf16 As[2][128][40];
    __shared__ __align__(16) bf16 Bs[2][128][40];

    const int tid = threadIdx.x, lane = tid & 31, warp = tid >> 5;
    const int wm = warp & 1, wn = warp >> 1;             // 2 x 4 warp grid
    const int m0 = blockIdx.y * 128, n0 = blockIdx.x * 128;
    const bf16* Ap = A + (size_t)m0 * K;
    const bf16* Bp = Bw + (size_t)n0 * K;

    float acc[4][4][4];
#pragma unroll
    for (int i = 0; i < 4; i++)
#pragma unroll
        for (int j = 0; j < 4; j++)
#pragma unroll
            for (int v = 0; v < 4; v++) acc[i][j][v] = 0.f;

    auto load = [&](int buf, int kt) {
#pragma unroll
        for (int i = 0; i < 2; i++) {
            int c = tid + i * 256;          // 0..511
            int row = c >> 2, col = (c & 3) << 3;
            cp16(&As[buf][row][col], Ap + (size_t)row * K + kt * 32 + col);
            cp16(&Bs[buf][row][col], Bp + (size_t)row * K + kt * 32 + col);
        }
    };

    load(0, 0);
    asm volatile("cp.async.commit_group;\n");
    constexpr int KT = K >> 5;
    int buf = 0;
#pragma unroll 1
    for (int kt = 0; kt < KT; kt++) {
        if (kt + 1 < KT) {
            load(buf ^ 1, kt + 1);
            asm volatile("cp.async.commit_group;\n");
            asm volatile("cp.async.wait_group 1;\n");
        } else {
            asm volatile("cp.async.wait_group 0;\n");
        }
        __syncthreads();
#pragma unroll
        for (int kh = 0; kh < 2; kh++) {
            const int kk = kh * 16;
            uint32_t af[4][4], bfr[4][2];
#pragma unroll
            for (int mi = 0; mi < 4; mi++)
                ldm4(af[mi], &As[buf][wm * 64 + mi * 16 + (lane & 15)][kk + ((lane >> 4) << 3)]);
#pragma unroll
            for (int ni = 0; ni < 4; ni++)
                ldm2(bfr[ni], &Bs[buf][wn * 32 + ni * 8 + (lane & 7)][kk + (((lane >> 3) & 1) << 3)]);
#pragma unroll
            for (int mi = 0; mi < 4; mi++)
#pragma unroll
                for (int ni = 0; ni < 4; ni++)
                    mma16816(acc[mi][ni], af[mi], bfr[ni]);
        }
        __syncthreads();
        buf ^= 1;
    }

    // epilogue
#pragma unroll
    for (int mi = 0; mi < 4; mi++) {
#pragma unroll
        for (int ni = 0; ni < 4; ni++) {
            int mA = m0 + wm * 64 + mi * 16 + (lane >> 2);
            int n = n0 + wn * 32 + ni * 8 + ((lane & 3) << 1);
#pragma unroll
            for (int h = 0; h < 2; h++) {
                int mm = mA + h * 8;
                float v0 = acc[mi][ni][h * 2 + 0];
                float v1 = acc[mi][ni][h * 2 + 1];
                size_t idx = (size_t)mm * N + n;
                if (SEL == 1) {
                    *reinterpret_cast<bf162*>(g_xr + idx) = __floats2bfloat162_rn(v0, v1);
                } else if (SEL == 2) {
                    v0 += g_b2[n]; v1 += g_b2[n + 1];
                    *reinterpret_cast<bf162*>(g_dtbc + idx) = __floats2bfloat162_rn(v0, v1);
                } else {
                    float x0 = clip10(resid[idx]);
                    float x1 = clip10(resid[idx + 1]);
                    *reinterpret_cast<float2*>(g_opre + idx) = make_float2(v0 + x0, v1 + x1);
                }
            }
        }
    }
}

// ---------------- causal depthwise conv(4) + SiLU ----------------
__global__ void k_conv(const float* __restrict__ cw, const float* __restrict__ cb) {
    size_t idx = (size_t)blockIdx.x * 256 + threadIdx.x;
    if (idx >= (size_t)ROWS * DI) return;
    int di = (int)(idx % DI);
    size_t row = idx / DI;
    int t = (int)(row % SEQ);
    float acc = cb[di];
#pragma unroll
    for (int k = 0; k < 4; k++) {
        int tt = t - 3 + k;
        if (tt >= 0)
            acc = fmaf(cw[di * 4 + k], bf2f(g_xr[(row - 3 + k) * N1 + di]), acc);
    }
    float sg = 1.f / (1.f + __expf(-acc));
    g_xc[idx] = f2bf(acc * sg);
}

// ---------------- selective scan ----------------
// thread = (b, di, q) ; q owns states ds = 4q..4q+3 ; warp covers 8 di x 4 q
__global__ void __launch_bounds__(128) k_scan(const float* __restrict__ A_log,
                                              const float* __restrict__ Dp) {
    const int b = blockIdx.x >> 5;
    const int diblk = blockIdx.x & 31;
    const int q = threadIdx.x & 3;
    const int di = diblk * 32 + (threadIdx.x >> 2);
    const float LOG2E = 1.4426950408889634f;
    const float CL = 5.0f * LOG2E;

    float A2[4];
#pragma unroll
    for (int j = 0; j < 4; j++) A2[j] = A_log[q * 4 + j] * LOG2E;
    const float Dv = Dp[di];

    float s0 = 0.f, s1 = 0.f, s2 = 0.f, s3 = 0.f;
    const size_t rb = (size_t)b * SEQ;

#pragma unroll 4
    for (int t = 0; t < SEQ; t++) {
        size_t row = rb + t;
        size_t base = row * N2;
        float dt = bf2f(g_dtbc[base + di]);
        float u = bf2f(g_xc[row * DI + di]);
        uint2 braw = *reinterpret_cast<const uint2*>(&g_dtbc[base + 1024 + 4 * q]);
        uint2 craw = *reinterpret_cast<const uint2*>(&g_dtbc[base + 1040 + 4 * q]);
        float2 Bl = bf2x(braw.x), Bh = bf2x(braw.y);
        float2 Cl = bf2x(craw.x), Ch = bf2x(craw.y);
        float du = dt * u;

        float z, dA, acc;
        z = fminf(fmaxf(dt * A2[0], -CL), CL); dA = ex2f(z);
        s0 = fmaf(dA, s0, du * Bl.x); acc = s0 * Cl.x;
        z = fminf(fmaxf(dt * A2[1], -CL), CL); dA = ex2f(z);
        s1 = fmaf(dA, s1, du * Bl.y); acc = fmaf(s1, Cl.y, acc);
        z = fminf(fmaxf(dt * A2[2], -CL), CL); dA = ex2f(z);
        s2 = fmaf(dA, s2, du * Bh.x); acc = fmaf(s2, Ch.x, acc);
        z = fminf(fmaxf(dt * A2[3], -CL), CL); dA = ex2f(z);
        s3 = fmaf(dA, s3, du * Bh.y); acc = fmaf(s3, Ch.y, acc);

        acc += __shfl_xor_sync(0xffffffffu, acc, 1);
        acc += __shfl_xor_sync(0xffffffffu, acc, 2);
        if (q == 0) g_y[row * DI + di] = f2bf(fmaf(u, Dv, acc));
    }
}

// ---------------- y2 = y * silu(res) ----------------
__global__ void k_mulsilu() {
    size_t idx = (size_t)blockIdx.x * 256 + threadIdx.x;
    if (idx >= (size_t)ROWS * DI) return;
    size_t row = idx / DI;
    int di = (int)(idx % DI);
    float yv = bf2f(g_y[idx]);
    float rv = bf2f(g_xr[row * N1 + 1024 + di]);
    float sg = 1.f / (1.f + __expf(-rv));
    g_y2[idx] = f2bf(yv * rv * sg);
}

// ---------------- LayerNorm (512, eps=1e-5), warp per row ----------------
__global__ void __launch_bounds__(256) k_ln(const float* __restrict__ gam,
                                            const float* __restrict__ bet,
                                            float* __restrict__ out) {
    int w = (blockIdx.x * 256 + threadIdx.x) >> 5;
    int lane = threadIdx.x & 31;
    if (w >= ROWS) return;
    const float* r = g_opre + (size_t)w * DM;
    float v[16], s = 0.f, ss = 0.f;
#pragma unroll
    for (int i = 0; i < 16; i++) {
        v[i] = r[i * 32 + lane];
        s += v[i];
        ss = fmaf(v[i], v[i], ss);
    }
#pragma unroll
    for (int o = 16; o; o >>= 1) {
        s += __shfl_xor_sync(0xffffffffu, s, o);
        ss += __shfl_xor_sync(0xffffffffu, ss, o);
    }
    float mu = s * (1.f / 512.f);
    float var = ss * (1.f / 512.f) - mu * mu;
    float rstd = rsqrtf(var + 1e-5f);
#pragma unroll
    for (int i = 0; i < 16; i++) {
        int c = i * 32 + lane;
        out[(size_t)w * DM + c] = (v[i] - mu) * rstd * gam[c] + bet[c];
    }
}

// ---------------- launch ----------------
extern "C" void kernel_launch(void* const* d_in, const int* in_sizes, int n_in,
                              void* d_out, int out_size) {
    const float* x      = (const float*)d_in[0];
    const float* W_in   = (const float*)d_in[1];
    const float* conv_w = (const float*)d_in[2];
    const float* conv_b = (const float*)d_in[3];
    const float* W_x    = (const float*)d_in[4];
    const float* W_dt   = (const float*)d_in[5];
    const float* b_dt   = (const float*)d_in[6];
    const float* A_log  = (const float*)d_in[7];
    const float* Dp     = (const float*)d_in[8];
    const float* W_out  = (const float*)d_in[9];
    const float* ln_g   = (const float*)d_in[10];
    const float* ln_b   = (const float*)d_in[11];
    float* out = (float*)d_out;

    // prep: weight conversions + input clip
    k_cvtW1<<<(N1 * DM + 255) / 256, 256>>>(W_in);
    k_cvtW3<<<(N3 * DI + 255) / 256, 256>>>(W_out);
    k_wcat<<<(N2 * DI + 255) / 256, 256>>>(W_dt, W_x);
    k_bias2<<<(N2 + 255) / 256, 256>>>(b_dt);
    k_clipx<<<(ROWS * DM + 255) / 256, 256>>>(x);

    // GEMM1: x_and_res = xb @ W_in^T   [32768, 2048]
    { dim3 grid(N1 / 128, ROWS / 128); k_gemm<1><<<grid, 256>>>(nullptr); }

    // conv + silu -> xc
    k_conv<<<(int)(((size_t)ROWS * DI + 255) / 256), 256>>>(conv_w, conv_b);

    // GEMM2: [dt | B | C | pad] = xc @ Wcat^T  [32768, 1152] (+bias)
    { dim3 grid(N2 / 128, ROWS / 128); k_gemm<2><<<grid, 256>>>(nullptr); }

    // selective scan -> y (includes + u*D)
    k_scan<<<B_SZ * 32, 128>>>(A_log, Dp);

    // y2 = y * silu(res)
    k_mulsilu<<<(int)(((size_t)ROWS * DI + 255) / 256), 256>>>();

    // GEMM3: opre = y2 @ W_out^T + clip(x)   [32768, 512] f32
    { dim3 grid(N3 / 128, ROWS / 128); k_gemm<3><<<grid, 256>>>(x); }

    // LayerNorm -> out
    k_ln<<<(ROWS * 32 + 255) / 256, 256>>>(ln_g, ln_b, out);
}